// round 3
// baseline (speedup 1.0000x reference)
#include <cuda_runtime.h>
#include <cuda_bf16.h>

// Problem constants (fixed by reference)
#define BATCH 16384
#define SEQ   7
#define EMBED 1024
#define E4    (EMBED / 4)        // 256 float4 lanes per row
#define ROWS_PER_CTA 8

// Round-3 A/B switch: 0 = accurate (2 MUFU: EX2+RCP), 1 = tanh.approx (1 MUFU).
// Held at 0 until a passing baseline pins rel_err headroom.
#define USE_TANH_SIGMOID 0

__device__ __forceinline__ float sigmoidf_fast(float x) {
#if USE_TANH_SIGMOID
    float t;
    asm("tanh.approx.f32 %0, %1;" : "=f"(t) : "f"(x * 0.5f));
    return fmaf(t, 0.5f, 0.5f);                  // 1 MUFU + 2 FMA-pipe ops
#else
    float e = exp2f(x * -1.4426950408889634f);   // MUFU.EX2 (direct, no reduction)
    return __fdividef(1.0f, 1.0f + e);           // MUFU.RCP
#endif
}

__global__ __launch_bounds__(E4, 4)
void CSM_62216896250023_kernel(const int*   __restrict__ X,     // (B, 7) int32
                               const float* __restrict__ emb,   // (32000, 1024)
                               const float4* __restrict__ c1,   // (2, 1024) as float4
                               const float4* __restrict__ c2,   // (2, 1024)
                               const float4* __restrict__ c3,   // (3, 1024)
                               const float4* __restrict__ c4,   // (3, 1024)
                               float4* __restrict__ out)        // (B, 1024)
{
    const int e4 = threadIdx.x;                 // 0..255 -> channels [e4*4, e4*4+4)
    const float4* __restrict__ emb4 = (const float4*)emb;

    // Hoist conv weights into registers: reused for all ROWS_PER_CTA rows.
    float4 w1[2], w2[2], w3[3], w4[3];
#pragma unroll
    for (int k = 0; k < 2; ++k) w1[k] = __ldg(&c1[k * E4 + e4]);
#pragma unroll
    for (int k = 0; k < 2; ++k) w2[k] = __ldg(&c2[k * E4 + e4]);
#pragma unroll
    for (int k = 0; k < 3; ++k) w3[k] = __ldg(&c3[k * E4 + e4]);
#pragma unroll
    for (int k = 0; k < 3; ++k) w4[k] = __ldg(&c4[k * E4 + e4]);

    const int row0 = blockIdx.x * ROWS_PER_CTA;
    const int* __restrict__ xrow = X + (size_t)row0 * SEQ;
    float4* __restrict__ orow = out + (size_t)row0 * E4 + e4;

#pragma unroll 1
    for (int r = 0; r < ROWS_PER_CTA; ++r) {
        // Token ids: uniform across the warp -> broadcast loads.
        int tok[SEQ];
#pragma unroll
        for (int t = 0; t < SEQ; ++t) tok[t] = __ldg(&xrow[r * SEQ + t]);

        // 7 independent gathers up front -> MLP=7, coalesced float4 per warp.
        float4 h4[SEQ];
#pragma unroll
        for (int t = 0; t < SEQ; ++t)
            h4[t] = __ldg(&emb4[(size_t)tok[t] * E4 + e4]);

        float4 o4;
        float* op = (float*)&o4;

        // Per-component scalar dataflow (4 channels per thread).
#pragma unroll
        for (int c = 0; c < 4; ++c) {
            float h[SEQ];
#pragma unroll
            for (int t = 0; t < SEQ; ++t) h[t] = ((const float*)&h4[t])[c];

            const float w10 = ((const float*)&w1[0])[c], w11 = ((const float*)&w1[1])[c];
            const float w20 = ((const float*)&w2[0])[c], w21 = ((const float*)&w2[1])[c];
            const float w30 = ((const float*)&w3[0])[c], w31 = ((const float*)&w3[1])[c],
                        w32 = ((const float*)&w3[2])[c];
            const float w40 = ((const float*)&w4[0])[c], w41 = ((const float*)&w4[1])[c],
                        w42 = ((const float*)&w4[2])[c];

            // Layer 1: h(7) -> a(6)
            float a[6];
#pragma unroll
            for (int t = 0; t < 6; ++t)
                a[t] = sigmoidf_fast(fmaf(h[t], w10, h[t + 1] * w11));

            // Layer 2: a(6) -> bb(5)
            float bb[5];
#pragma unroll
            for (int t = 0; t < 5; ++t)
                bb[t] = sigmoidf_fast(fmaf(a[t], w20, a[t + 1] * w21));

            // Layer 3: bb(5) -> cc(3)   (kernel height 3)
            float cc[3];
#pragma unroll
            for (int t = 0; t < 3; ++t)
                cc[t] = sigmoidf_fast(fmaf(bb[t], w30,
                                      fmaf(bb[t + 1], w31, bb[t + 2] * w32)));

            // Layer 4: cc(3) -> scalar
            op[c] = sigmoidf_fast(fmaf(cc[0], w40, fmaf(cc[1], w41, cc[2] * w42)));
        }

        orow[r * E4] = o4;
    }
}

extern "C" void kernel_launch(void* const* d_in, const int* in_sizes, int n_in,
                              void* d_out, int out_size) {
    const int*    X   = (const int*)   d_in[0];
    const float*  emb = (const float*) d_in[1];
    const float4* c1  = (const float4*)d_in[2];
    const float4* c2  = (const float4*)d_in[3];
    const float4* c3  = (const float4*)d_in[4];
    const float4* c4  = (const float4*)d_in[5];
    float4* out = (float4*)d_out;

    dim3 grid(BATCH / ROWS_PER_CTA);   // 2048 CTAs
    dim3 block(E4);                    // 256 threads, 4 channels each
    CSM_62216896250023_kernel<<<grid, block>>>(X, emb, c1, c2, c3, c4, out);
}

// round 11
// speedup vs baseline: 1.2804x; 1.2804x over previous
#include <cuda_runtime.h>
#include <cuda_bf16.h>

// Problem constants (fixed by reference)
#define BATCH 16384
#define SEQ   7
#define EMBED 1024
#define E4    (EMBED / 4)        // 256 float4 lanes per row
#define ROWS_PER_CTA 8

// sigmoid(y) = 0.5*tanh(y/2) + 0.5. The affine (0.5, +0.5) is never
// materialized: downstream conv layers absorb it into quarter-scaled weights
// plus a per-channel bias (see weight prep). Inner activations ride in
// t-domain, costing exactly 1 MUFU.TANH each.
__device__ __forceinline__ float tanh_apx(float x) {
    float t;
    asm("tanh.approx.f32 %0, %1;" : "=f"(t) : "f"(x));
    return t;
}

// Final-layer sigmoid stays accurate: EX2 + RCP (~2 ulp), protects rel_err.
__device__ __forceinline__ float sigmoid_accurate(float x) {
    float e = exp2f(x * -1.4426950408889634f);   // MUFU.EX2
    return __fdividef(1.0f, 1.0f + e);           // MUFU.RCP
}

__global__ __launch_bounds__(E4, 4)
void CSM_62216896250023_kernel(const int*   __restrict__ X,     // (B, 7) int32
                               const float* __restrict__ emb,   // (32000, 1024)
                               const float4* __restrict__ c1,   // (2, 1024) as float4
                               const float4* __restrict__ c2,   // (2, 1024)
                               const float4* __restrict__ c3,   // (3, 1024)
                               const float4* __restrict__ c4,   // (3, 1024)
                               float4* __restrict__ out)        // (B, 1024)
{
    const int e4 = threadIdx.x;                 // 0..255 -> channels [e4*4, e4*4+4)
    const float4* __restrict__ emb4 = (const float4*)emb;

    // ---- Weight prep (once per thread, amortized over ROWS_PER_CTA rows) ----
    // Layer 1 inputs are raw embeddings:      a  = tanh( (w1/2)·h )
    // Layers 2,3 inputs are s = 0.5 t + 0.5:  y/2 = Σ (w/4)·t + Σ w/4
    // Layer 4 feeds accurate sigmoid (no /2): y4  = Σ (w/2)·t + Σ w/2
    float u1[2][4], v2[2][4], v3[3][4], q4[3][4], b2[4], b3[4], b4[4];
    {
        float4 w1[2], w2[2], w3[3], w4[3];
#pragma unroll
        for (int k = 0; k < 2; ++k) w1[k] = __ldg(&c1[k * E4 + e4]);
#pragma unroll
        for (int k = 0; k < 2; ++k) w2[k] = __ldg(&c2[k * E4 + e4]);
#pragma unroll
        for (int k = 0; k < 3; ++k) w3[k] = __ldg(&c3[k * E4 + e4]);
#pragma unroll
        for (int k = 0; k < 3; ++k) w4[k] = __ldg(&c4[k * E4 + e4]);

#pragma unroll
        for (int c = 0; c < 4; ++c) {
            const float w10 = ((const float*)&w1[0])[c], w11 = ((const float*)&w1[1])[c];
            const float w20 = ((const float*)&w2[0])[c], w21 = ((const float*)&w2[1])[c];
            const float w30 = ((const float*)&w3[0])[c], w31 = ((const float*)&w3[1])[c],
                        w32 = ((const float*)&w3[2])[c];
            const float w40 = ((const float*)&w4[0])[c], w41 = ((const float*)&w4[1])[c],
                        w42 = ((const float*)&w4[2])[c];
            u1[0][c] = w10 * 0.5f;  u1[1][c] = w11 * 0.5f;
            v2[0][c] = w20 * 0.25f; v2[1][c] = w21 * 0.25f;
            b2[c]    = (w20 + w21) * 0.25f;
            v3[0][c] = w30 * 0.25f; v3[1][c] = w31 * 0.25f; v3[2][c] = w32 * 0.25f;
            b3[c]    = (w30 + w31 + w32) * 0.25f;
            q4[0][c] = w40 * 0.5f;  q4[1][c] = w41 * 0.5f;  q4[2][c] = w42 * 0.5f;
            b4[c]    = (w40 + w41 + w42) * 0.5f;
        }
    }

    const int row0 = blockIdx.x * ROWS_PER_CTA;
    const int* __restrict__ xrow = X + (size_t)row0 * SEQ;
    float4* __restrict__ orow = out + (size_t)row0 * E4 + e4;

#pragma unroll 1
    for (int r = 0; r < ROWS_PER_CTA; ++r) {
        // Token ids: uniform across the warp -> broadcast loads.
        int tok[SEQ];
#pragma unroll
        for (int t = 0; t < SEQ; ++t) tok[t] = __ldg(&xrow[r * SEQ + t]);

        // 7 independent gathers up front -> MLP=7, coalesced float4 per warp.
        float4 h4[SEQ];
#pragma unroll
        for (int t = 0; t < SEQ; ++t)
            h4[t] = __ldg(&emb4[(size_t)tok[t] * E4 + e4]);

        float4 o4;
        float* op = (float*)&o4;

        // Per-component scalar dataflow (4 channels per thread).
#pragma unroll
        for (int c = 0; c < 4; ++c) {
            float h[SEQ];
#pragma unroll
            for (int t = 0; t < SEQ; ++t) h[t] = ((const float*)&h4[t])[c];

            // Layer 1: h(7) -> t-domain a(6).
            float a[6];
#pragma unroll
            for (int t = 0; t < 6; ++t)
                a[t] = tanh_apx(fmaf(h[t + 1], u1[1][c], h[t] * u1[0][c]));

            // Layer 2: a(6) -> bb(5).
            float bb[5];
#pragma unroll
            for (int t = 0; t < 5; ++t)
                bb[t] = tanh_apx(fmaf(a[t], v2[0][c],
                                 fmaf(a[t + 1], v2[1][c], b2[c])));

            // Layer 3: bb(5) -> cc(3).
            float cc[3];
#pragma unroll
            for (int t = 0; t < 3; ++t)
                cc[t] = tanh_apx(fmaf(bb[t], v3[0][c],
                                 fmaf(bb[t + 1], v3[1][c],
                                 fmaf(bb[t + 2], v3[2][c], b3[c]))));

            // Layer 4: cc(3) -> scalar, accurate sigmoid.
            const float y4 = fmaf(cc[0], q4[0][c],
                             fmaf(cc[1], q4[1][c],
                             fmaf(cc[2], q4[2][c], b4[c])));
            op[c] = sigmoid_accurate(y4);
        }

        orow[r * E4] = o4;
    }
}

extern "C" void kernel_launch(void* const* d_in, const int* in_sizes, int n_in,
                              void* d_out, int out_size) {
    const int*    X   = (const int*)   d_in[0];
    const float*  emb = (const float*) d_in[1];
    const float4* c1  = (const float4*)d_in[2];
    const float4* c2  = (const float4*)d_in[3];
    const float4* c3  = (const float4*)d_in[4];
    const float4* c4  = (const float4*)d_in[5];
    float4* out = (float4*)d_out;

    dim3 grid(BATCH / ROWS_PER_CTA);   // 2048 CTAs
    dim3 block(E4);                    // 256 threads, 4 channels each
    CSM_62216896250023_kernel<<<grid, block>>>(X, emb, c1, c2, c3, c4, out);
}